// round 10
// baseline (speedup 1.0000x reference)
#include <cuda_runtime.h>
#include <cuda_bf16.h>
#include <math.h>
#include <cstdint>

#define B_   2
#define S_   2048
#define D_   1024
#define H_   16
#define HD_  64
#define M_   (B_ * S_)      // 4096
#define NQKV (3 * D_)       // 3072

// ---------------- scratch (static device globals; no allocation) ----------
__device__ float g_x32[(size_t)M_ * D_];        // tf32-rounded, k16-permuted
__device__ float g_wq32[(size_t)NQKV * D_];
__device__ float g_wo32[(size_t)D_ * D_];
__device__ float g_q32[(size_t)M_ * D_];        // [B,H,S,perm16(d)]
__device__ float g_k32[(size_t)M_ * D_];        // [B,H,S,perm16(d)]
__device__ float g_vT32[(size_t)M_ * D_];       // [B,H,d,perm16_s(S)]
__device__ float g_o32[(size_t)M_ * D_];        // [B*S, perm16(D)]
__device__ float g_invfreq[32];                 // rope inv frequencies

// =====================  helpers  ===========================================
__device__ __forceinline__ uint32_t smem_u32(const void* p) {
    uint32_t a;
    asm("{ .reg .u64 t; cvta.to.shared.u64 t, %1; cvt.u32.u64 %0, t; }"
        : "=r"(a) : "l"(p));
    return a;
}
__device__ __forceinline__ float rna_tf32(float x) {
    uint32_t u;
    asm("cvt.rna.tf32.f32 %0, %1;" : "=r"(u) : "f"(x));
    return __uint_as_float(u);
}
__device__ __forceinline__ void mma_tf32(float (&d)[4], const uint32_t (&a)[4],
                                         uint32_t b0, uint32_t b1) {
    asm volatile(
        "mma.sync.aligned.m16n8k8.row.col.f32.tf32.tf32.f32 "
        "{%0,%1,%2,%3}, {%4,%5,%6,%7}, {%8,%9}, {%0,%1,%2,%3};"
        : "+f"(d[0]), "+f"(d[1]), "+f"(d[2]), "+f"(d[3])
        : "r"(a[0]), "r"(a[1]), "r"(a[2]), "r"(a[3]), "r"(b0), "r"(b1));
}
__device__ __forceinline__ void cp16(uint32_t saddr, const void* gaddr) {
    asm volatile("cp.async.cg.shared.global [%0], [%1], 16;"
        :: "r"(saddr), "l"(gaddr));
}
#define CP_COMMIT() asm volatile("cp.async.commit_group;" ::: "memory")
#define CP_WAIT(n)  asm volatile("cp.async.wait_group %0;" :: "n"(n) : "memory")

// 16-wide k permutation: thread t's 4 values for 2 k-steps become one float4
__host__ __device__ __forceinline__ int p16(int u) {
    return ((u & 3) << 2) | ((u >> 2) & 3);
}
__host__ __device__ __forceinline__ int permk16(int k) {
    return (k & ~15) | p16(k & 15);
}

// ---------------------------------------------------------------------------
__global__ void init_invfreq(float* invf) {
    int j = threadIdx.x;                    // 0..31
    float tt = (float)(2 * j) * (1.0f / (float)HD_);
    invf[j] = powf(10000.0f, -tt);
}

// ---------------------------------------------------------------------------
// cvt + permute (vectorized x4): dst[r][permk16(c)] = rna_tf32(src[r][c])
// ---------------------------------------------------------------------------
__global__ void cvt_perm4(const float* __restrict__ src, float* __restrict__ dst,
                          int n4, int cols)
{
    int i = blockIdx.x * blockDim.x + threadIdx.x;
    if (i >= n4) return;
    int cols4 = cols >> 2;
    int r  = i / cols4;
    int cq = i - r * cols4;
    float4 v = ((const float4*)src)[i];
    int q      = cq & 3;
    int base16 = (cq >> 2) << 4;
    float* drow = dst + (size_t)r * cols + base16 + q;
    drow[0]  = rna_tf32(v.x);
    drow[4]  = rna_tf32(v.y);
    drow[8]  = rna_tf32(v.z);
    drow[12] = rna_tf32(v.w);
}

#define G_BOFF 32768               // B tile offset within stage (A = 256*128B)
#define G_STG  49152               // 48KB per stage
#define GEMM_SMEM (3 * G_STG)      // 147456

// ---------------------------------------------------------------------------
// Shared mainloop: CTA 256x128, 8 warps, warp tile 64x64, K-chunk 32,
// 3-stage cp.async. (identical numerics across both GEMM kernels)
// ---------------------------------------------------------------------------
#define GEMM_MAINLOOP(Aptr, Bptr, Kdim)                                        \
    const uint32_t sb = smem_u32(sm);                                          \
    const int tid  = threadIdx.x;                                              \
    const int lane = tid & 31;                                                 \
    const int w    = tid >> 5;                                                 \
    const int g    = lane >> 2;                                                \
    const int t    = lane & 3;                                                 \
    const int m0 = blockIdx.y * 256;                                           \
    const int n0 = blockIdx.x * 128;                                           \
    const int wm = (w & 3) * 64;                                               \
    const int wn = (w >> 2) * 64;                                              \
    float acc[4][8][4];                                                        \
    _Pragma("unroll")                                                          \
    for (int mi = 0; mi < 4; ++mi)                                             \
        _Pragma("unroll")                                                      \
        for (int nj = 0; nj < 8; ++nj)                                         \
            _Pragma("unroll")                                                  \
            for (int q = 0; q < 4; ++q) acc[mi][nj][q] = 0.f;                  \
    const int nch = (Kdim) >> 5;                                               \
    auto issue = [&](int kc, int stg) {                                        \
        uint32_t st = sb + stg * G_STG;                                        \
        _Pragma("unroll")                                                      \
        for (int it = 0; it < 8; ++it) {                                       \
            int idx = tid + it * 256;                                          \
            int r = idx >> 3, c = idx & 7;                                     \
            uint32_t so = r * 128 + (((uint32_t)(c ^ ((r & 1) << 2))) << 4);   \
            cp16(st + so, (Aptr) + (size_t)(m0 + r) * (Kdim) + kc * 32 + c * 4); \
        }                                                                      \
        _Pragma("unroll")                                                      \
        for (int it = 0; it < 4; ++it) {                                       \
            int idx = tid + it * 256;                                          \
            int r = idx >> 3, c = idx & 7;                                     \
            uint32_t so = r * 128 + (((uint32_t)(c ^ ((r & 1) << 2))) << 4);   \
            cp16(st + G_BOFF + so, (Bptr) + (size_t)(n0 + r) * (Kdim) + kc * 32 + c * 4); \
        }                                                                      \
        CP_COMMIT();                                                           \
    };                                                                         \
    issue(0, 0);                                                               \
    if (nch > 1) issue(1, 1);                                                  \
    for (int kc = 0; kc < nch; ++kc) {                                         \
        if (kc + 1 < nch) { CP_WAIT(1); }                                      \
        else              { CP_WAIT(0); }                                      \
        __syncthreads();                                                       \
        if (kc + 2 < nch) issue(kc + 2, (kc + 2) % 3);                         \
        char* st = sm + (kc % 3) * G_STG;                                      \
        _Pragma("unroll")                                                      \
        for (int ks2 = 0; ks2 < 2; ++ks2) {                                    \
            float4 bf[8];                                                      \
            _Pragma("unroll")                                                  \
            for (int nj = 0; nj < 8; ++nj) {                                   \
                int r = wn + nj * 8 + g;                                       \
                int c = (ks2 * 4 + t) ^ ((r & 1) << 2);                        \
                bf[nj] = *(float4*)(st + G_BOFF + r * 128 + c * 16);           \
            }                                                                  \
            _Pragma("unroll")                                                  \
            for (int mi = 0; mi < 4; ++mi) {                                   \
                int r0 = wm + mi * 16 + g;                                     \
                int c  = (ks2 * 4 + t) ^ ((r0 & 1) << 2);                      \
                float4 lo = *(float4*)(st + r0 * 128 + c * 16);                \
                float4 hi = *(float4*)(st + (r0 + 8) * 128 + c * 16);          \
                uint32_t ae[4] = {__float_as_uint(lo.x), __float_as_uint(hi.x),\
                                  __float_as_uint(lo.y), __float_as_uint(hi.y)};\
                uint32_t ao[4] = {__float_as_uint(lo.z), __float_as_uint(hi.z),\
                                  __float_as_uint(lo.w), __float_as_uint(hi.w)};\
                _Pragma("unroll")                                              \
                for (int nj = 0; nj < 8; ++nj)                                 \
                    mma_tf32(acc[mi][nj], ae, __float_as_uint(bf[nj].x),       \
                             __float_as_uint(bf[nj].y));                       \
                _Pragma("unroll")                                              \
                for (int nj = 0; nj < 8; ++nj)                                 \
                    mma_tf32(acc[mi][nj], ao, __float_as_uint(bf[nj].z),       \
                             __float_as_uint(bf[nj].w));                       \
            }                                                                  \
        }                                                                      \
    }

// ---------------------------------------------------------------------------
// Generic GEMM (out projection): epilogue = bias + fp32 store
// ---------------------------------------------------------------------------
__global__ void __launch_bounds__(256, 1) gemm_tf32(
    const float* __restrict__ A, const float* __restrict__ Bw,
    const float* __restrict__ bias, float* __restrict__ C,
    int M, int N, int K)
{
    extern __shared__ char sm[];
    GEMM_MAINLOOP(A, Bw, K)

    const int c0 = t * 2;
#pragma unroll
    for (int mi = 0; mi < 4; ++mi) {
#pragma unroll
        for (int nj = 0; nj < 8; ++nj) {
            int m = m0 + wm + mi * 16 + g;
            int n = n0 + wn + nj * 8 + c0;
            float b0 = bias ? bias[n] : 0.f;
            float b1 = bias ? bias[n + 1] : 0.f;
            float2 v0 = {acc[mi][nj][0] + b0, acc[mi][nj][1] + b1};
            float2 v1 = {acc[mi][nj][2] + b0, acc[mi][nj][3] + b1};
            *(float2*)(C + (size_t)m * N + n)       = v0;
            *(float2*)(C + (size_t)(m + 8) * N + n) = v1;
        }
    }
}

// ---------------------------------------------------------------------------
// QKV GEMM with fused RoPE epilogue.
// q/k tiles: transpose through smem, rope per s-row, coalesced float4 stores.
// v tiles:   direct scatter (s-consecutive lanes share sectors).
// Arithmetic identical to the old rope_tf32 kernel (same formulas, same rna).
// ---------------------------------------------------------------------------
__global__ void __launch_bounds__(256, 1) gemm_qkv_rope(
    const float* __restrict__ A, const float* __restrict__ Bw,
    float* __restrict__ q32, float* __restrict__ k32, float* __restrict__ vT,
    const float* __restrict__ invfreq, int M, int N, int K)
{
    extern __shared__ char sm[];
    GEMM_MAINLOOP(A, Bw, K)

    const int tile_type = n0 >> 10;          // 0=q, 1=k, 2=v
    const int hbase = (n0 & 1023) >> 6;

    if (tile_type < 2) {
        // --- stage the 256x128 fp32 tile in smem (pad 132 floats/row) ---
        float* smemf = (float*)sm;
        __syncthreads();                     // mainloop reads done
#pragma unroll
        for (int mi = 0; mi < 4; ++mi)
#pragma unroll
            for (int nj = 0; nj < 8; ++nj) {
                int rl = wm + mi * 16 + g;
                int cl = wn + nj * 8 + 2 * t;
                smemf[rl * 132 + cl]           = acc[mi][nj][0];
                smemf[rl * 132 + cl + 1]       = acc[mi][nj][1];
                smemf[(rl + 8) * 132 + cl]     = acc[mi][nj][2];
                smemf[(rl + 8) * 132 + cl + 1] = acc[mi][nj][3];
            }
        __syncthreads();

        const float scale = (tile_type == 0) ? 0.125f : 1.0f;
        float* dst = (tile_type == 0) ? q32 : k32;
#pragma unroll
        for (int e = 0; e < 2; ++e) {
            int job = tid + e * 256;         // 512 jobs: 256 rows x 2 heads
            int rl  = job & 255;
            int hl  = job >> 8;
            int m   = m0 + rl;
            int s   = m & (S_ - 1);
            int bb  = m >> 11;
            const float* src = smemf + rl * 132 + hl * 64;
            size_t obase = (((size_t)(bb * H_ + hbase + hl)) * S_ + s) * (size_t)HD_;
            float outbuf[64];
#pragma unroll
            for (int j = 0; j < 32; ++j) {
                float x1 = src[2 * j], x2 = src[2 * j + 1];
                float cs, sn;
                sincosf((float)s * invfreq[j], &sn, &cs);
                outbuf[permk16(j)]      = rna_tf32((x1 * cs - x2 * sn) * scale);
                outbuf[permk16(j + 32)] = rna_tf32((x1 * sn + x2 * cs) * scale);
            }
#pragma unroll
            for (int u = 0; u < 16; ++u)
                *(float4*)(dst + obase + u * 4) = *(const float4*)(outbuf + u * 4);
        }
    } else {
        // --- v: direct transpose-scatter to vT[B,H,d,perm16(s)] ---
#pragma unroll
        for (int nj = 0; nj < 8; ++nj) {
            int nn = wn + nj * 8 + 2 * t;    // 0..126 within tile
            int h  = hbase + (nn >> 6);
            int d  = nn & 63;
#pragma unroll
            for (int mi = 0; mi < 4; ++mi) {
#pragma unroll
                for (int rr = 0; rr < 2; ++rr) {
                    int m  = m0 + wm + mi * 16 + g + rr * 8;
                    int s  = m & (S_ - 1);
                    int bb = m >> 11;
                    int sp = (s & ~15) | p16(s & 15);
                    size_t base = ((size_t)(bb * H_ + h)) * HD_;
                    vT[(base + d)     * S_ + sp] = rna_tf32(acc[mi][nj][rr * 2 + 0]);
                    vT[(base + d + 1) * S_ + sp] = rna_tf32(acc[mi][nj][rr * 2 + 1]);
                }
            }
        }
    }
}

// ---------------------------------------------------------------------------
// Flash attention, tf32 mma. 128 threads (4 warps), 32 q-rows/warp
// (q-tile 128), kv-tile 32, 3-stage cp.async. (unchanged from round 9)
// ---------------------------------------------------------------------------
#define A_VOFF 8192
#define A_STG  16384
#define ATT_SMEM (3 * A_STG)       // 49152

__global__ void __launch_bounds__(128, 2) attn_tf32(
    const float* __restrict__ q_, const float* __restrict__ k_,
    const float* __restrict__ vT_, float* __restrict__ o_)
{
    extern __shared__ char sm[];
    const uint32_t sb = smem_u32(sm);
    const int tid  = threadIdx.x;
    const int lane = tid & 31;
    const int w    = tid >> 5;
    const int g    = lane >> 2;
    const int t    = lane & 3;
    const int q0 = blockIdx.x * 128;
    const int h  = blockIdx.y;
    const int b  = blockIdx.z;
    const size_t bh   = ((size_t)(b * H_ + h)) * S_;
    const size_t bh64 = ((size_t)(b * H_ + h)) * HD_;

#pragma unroll
    for (int it = 0; it < 16; ++it) {
        int idx = tid + it * 128;
        int r = idx >> 4, c = idx & 15;
        uint32_t so = r * 256 + (((uint32_t)(c ^ ((r & 1) << 2))) << 4);
        cp16(sb + so, q_ + (bh + q0 + r) * HD_ + c * 4);
    }
    CP_COMMIT();
    CP_WAIT(0);
    __syncthreads();

    uint32_t qf[2][8][4];
#pragma unroll
    for (int rs = 0; rs < 2; ++rs) {
        int r0 = w * 32 + rs * 16 + g;
#pragma unroll
        for (int ks2 = 0; ks2 < 4; ++ks2) {
            int c = (ks2 * 4 + t) ^ ((r0 & 1) << 2);
            float4 lo = *(float4*)(sm + r0 * 256 + c * 16);
            float4 hi = *(float4*)(sm + (r0 + 8) * 256 + c * 16);
            qf[rs][ks2*2][0]   = __float_as_uint(lo.x);
            qf[rs][ks2*2][1]   = __float_as_uint(hi.x);
            qf[rs][ks2*2][2]   = __float_as_uint(lo.y);
            qf[rs][ks2*2][3]   = __float_as_uint(hi.y);
            qf[rs][ks2*2+1][0] = __float_as_uint(lo.z);
            qf[rs][ks2*2+1][1] = __float_as_uint(hi.z);
            qf[rs][ks2*2+1][2] = __float_as_uint(lo.w);
            qf[rs][ks2*2+1][3] = __float_as_uint(hi.w);
        }
    }
    __syncthreads();

    auto issue_kv = [&](int n0k, int stg) {
        uint32_t st = sb + stg * A_STG;
#pragma unroll
        for (int it = 0; it < 4; ++it) {
            int idx = tid + it * 128;
            int r = idx >> 4, c = idx & 15;
            uint32_t so = r * 256 + (((uint32_t)(c ^ ((r & 1) << 2))) << 4);
            cp16(st + so, k_ + (bh + n0k + r) * HD_ + c * 4);
        }
#pragma unroll
        for (int it = 0; it < 4; ++it) {
            int idx = tid + it * 128;
            int r = idx >> 3, c = idx & 7;
            uint32_t so = r * 128 + (((uint32_t)(c ^ ((r & 1) << 2))) << 4);
            cp16(st + A_VOFF + so, vT_ + (bh64 + r) * S_ + n0k + c * 4);
        }
        CP_COMMIT();
    };

    issue_kv(0, 0);
    issue_kv(32, 1);

    float oacc[2][8][4];
    float mx[2][2] = {{-1e30f, -1e30f}, {-1e30f, -1e30f}};
    float li[2][2] = {{0.f, 0.f}, {0.f, 0.f}};
#pragma unroll
    for (int rs = 0; rs < 2; ++rs)
#pragma unroll
        for (int dj = 0; dj < 8; ++dj)
#pragma unroll
            for (int q = 0; q < 4; ++q) oacc[rs][dj][q] = 0.f;

    const int src0 = (lane & ~3) | (t >> 1);
    const int src1 = src0 + 2;

    const int nkv = S_ / 32;
    for (int kc = 0; kc < nkv; ++kc) {
        if (kc + 1 < nkv) { CP_WAIT(1); }
        else              { CP_WAIT(0); }
        __syncthreads();
        if (kc + 2 < nkv) issue_kv((kc + 2) * 32, (kc + 2) % 3);
        char* st = sm + (kc % 3) * A_STG;

        float s[2][4][4];
#pragma unroll
        for (int rs = 0; rs < 2; ++rs)
#pragma unroll
            for (int nj = 0; nj < 4; ++nj)
#pragma unroll
                for (int q = 0; q < 4; ++q) s[rs][nj][q] = 0.f;

#pragma unroll
        for (int ks2 = 0; ks2 < 4; ++ks2) {
            float4 kv4[4];
#pragma unroll
            for (int nj = 0; nj < 4; ++nj) {
                int r = nj * 8 + g;
                int c = (ks2 * 4 + t) ^ ((r & 1) << 2);
                kv4[nj] = *(float4*)(st + r * 256 + c * 16);
            }
#pragma unroll
            for (int rs = 0; rs < 2; ++rs)
#pragma unroll
                for (int nj = 0; nj < 4; ++nj)
                    mma_tf32(s[rs][nj], qf[rs][ks2*2],
                             __float_as_uint(kv4[nj].x),
                             __float_as_uint(kv4[nj].y));
#pragma unroll
            for (int rs = 0; rs < 2; ++rs)
#pragma unroll
                for (int nj = 0; nj < 4; ++nj)
                    mma_tf32(s[rs][nj], qf[rs][ks2*2+1],
                             __float_as_uint(kv4[nj].z),
                             __float_as_uint(kv4[nj].w));
        }

#pragma unroll
        for (int rs = 0; rs < 2; ++rs) {
#pragma unroll
            for (int ri = 0; ri < 2; ++ri) {
                float rm = -1e30f;
#pragma unroll
                for (int nj = 0; nj < 4; ++nj)
                    rm = fmaxf(rm, fmaxf(s[rs][nj][ri*2], s[rs][nj][ri*2+1]));
                rm = fmaxf(rm, __shfl_xor_sync(0xffffffffu, rm, 1));
                rm = fmaxf(rm, __shfl_xor_sync(0xffffffffu, rm, 2));
                float mn   = fmaxf(mx[rs][ri], rm);
                float corr = __expf(mx[rs][ri] - mn);
                mx[rs][ri] = mn;
                float rsum = 0.f;
#pragma unroll
                for (int nj = 0; nj < 4; ++nj) {
                    float p0 = __expf(s[rs][nj][ri*2]   - mn);
                    float p1 = __expf(s[rs][nj][ri*2+1] - mn);
                    s[rs][nj][ri*2] = p0; s[rs][nj][ri*2+1] = p1;
                    rsum += p0 + p1;
                }
                rsum += __shfl_xor_sync(0xffffffffu, rsum, 1);
                rsum += __shfl_xor_sync(0xffffffffu, rsum, 2);
                li[rs][ri] = li[rs][ri] * corr + rsum;
#pragma unroll
                for (int dj = 0; dj < 8; ++dj) {
                    oacc[rs][dj][ri*2]   *= corr;
                    oacc[rs][dj][ri*2+1] *= corr;
                }
            }
        }

#pragma unroll
        for (int kk2 = 0; kk2 < 2; ++kk2) {
            uint32_t pa[2][2][4];
#pragma unroll
            for (int rs = 0; rs < 2; ++rs)
#pragma unroll
                for (int e = 0; e < 2; ++e) {
                    int kk = kk2 * 2 + e;
                    float y00 = __shfl_sync(0xffffffffu, s[rs][kk][0], src0);
                    float y01 = __shfl_sync(0xffffffffu, s[rs][kk][1], src0);
                    float y10 = __shfl_sync(0xffffffffu, s[rs][kk][0], src1);
                    float y11 = __shfl_sync(0xffffffffu, s[rs][kk][1], src1);
                    float y20 = __shfl_sync(0xffffffffu, s[rs][kk][2], src0);
                    float y21 = __shfl_sync(0xffffffffu, s[rs][kk][3], src0);
                    float y30 = __shfl_sync(0xffffffffu, s[rs][kk][2], src1);
                    float y31 = __shfl_sync(0xffffffffu, s[rs][kk][3], src1);
                    pa[rs][e][0] = __float_as_uint(rna_tf32((t & 1) ? y01 : y00));
                    pa[rs][e][1] = __float_as_uint(rna_tf32((t & 1) ? y21 : y20));
                    pa[rs][e][2] = __float_as_uint(rna_tf32((t & 1) ? y11 : y10));
                    pa[rs][e][3] = __float_as_uint(rna_tf32((t & 1) ? y31 : y30));
                }
#pragma unroll
            for (int djg = 0; djg < 2; ++djg) {
                float4 vv[4];
#pragma unroll
                for (int u = 0; u < 4; ++u) {
                    int dj = djg * 4 + u;
                    int r = dj * 8 + g;
                    int c = (kk2 * 4 + t) ^ ((r & 1) << 2);
                    vv[u] = *(float4*)(st + A_VOFF + r * 128 + c * 16);
                }
#pragma unroll
                for (int u = 0; u < 4; ++u)
#pragma unroll
                    for (int rs = 0; rs < 2; ++rs)
                        mma_tf32(oacc[rs][djg*4+u], pa[rs][0],
                                 __float_as_uint(vv[u].x),
                                 __float_as_uint(vv[u].y));
#pragma unroll
                for (int u = 0; u < 4; ++u)
#pragma unroll
                    for (int rs = 0; rs < 2; ++rs)
                        mma_tf32(oacc[rs][djg*4+u], pa[rs][1],
                                 __float_as_uint(vv[u].z),
                                 __float_as_uint(vv[u].w));
            }
        }
    }

#pragma unroll
    for (int rs = 0; rs < 2; ++rs) {
#pragma unroll
        for (int ri = 0; ri < 2; ++ri) {
            float inv = 1.0f / li[rs][ri];
            int srow = q0 + w * 32 + rs * 16 + g + ri * 8;
            size_t rowo = ((size_t)(b * S_) + srow) * D_ + h * HD_;
#pragma unroll
            for (int dj = 0; dj < 8; ++dj) {
                int c = dj * 8 + 2 * t;
                o_[rowo + permk16(c)]     = rna_tf32(oacc[rs][dj][ri*2]   * inv);
                o_[rowo + permk16(c + 1)] = rna_tf32(oacc[rs][dj][ri*2+1] * inv);
            }
        }
    }
}

// ---------------------------------------------------------------------------
extern "C" void kernel_launch(void* const* d_in, const int* in_sizes, int n_in,
                              void* d_out, int out_size)
{
    (void)in_sizes; (void)n_in; (void)out_size;
    const float* x     = (const float*)d_in[0];
    const float* w_qkv = (const float*)d_in[1];
    const float* w_out = (const float*)d_in[2];
    const float* b_out = (const float*)d_in[3];
    float* out = (float*)d_out;

    float *p_x, *p_wq, *p_wo, *p_q, *p_k, *p_vT, *p_o, *p_if;
    cudaGetSymbolAddress((void**)&p_x,   g_x32);
    cudaGetSymbolAddress((void**)&p_wq,  g_wq32);
    cudaGetSymbolAddress((void**)&p_wo,  g_wo32);
    cudaGetSymbolAddress((void**)&p_q,   g_q32);
    cudaGetSymbolAddress((void**)&p_k,   g_k32);
    cudaGetSymbolAddress((void**)&p_vT,  g_vT32);
    cudaGetSymbolAddress((void**)&p_o,   g_o32);
    cudaGetSymbolAddress((void**)&p_if,  g_invfreq);

    cudaFuncSetAttribute(gemm_tf32,
        cudaFuncAttributeMaxDynamicSharedMemorySize, GEMM_SMEM);
    cudaFuncSetAttribute(gemm_qkv_rope,
        cudaFuncAttributeMaxDynamicSharedMemorySize, GEMM_SMEM);
    cudaFuncSetAttribute(attn_tf32,
        cudaFuncAttributeMaxDynamicSharedMemorySize, ATT_SMEM);

    // 0) rope tables + round+permute inputs / weights
    init_invfreq<<<1, 32>>>(p_if);
    {
        int n4;
        n4 = (M_ * D_) / 4;
        cvt_perm4<<<(n4 + 255) / 256, 256>>>(x, p_x, n4, D_);
        n4 = (NQKV * D_) / 4;
        cvt_perm4<<<(n4 + 255) / 256, 256>>>(w_qkv, p_wq, n4, D_);
        n4 = (D_ * D_) / 4;
        cvt_perm4<<<(n4 + 255) / 256, 256>>>(w_out, p_wo, n4, D_);
    }
    // 1) QKV projection + fused RoPE/permute epilogue
    {
        dim3 grid(NQKV / 128, M_ / 256);
        gemm_qkv_rope<<<grid, 256, GEMM_SMEM>>>(p_x, p_wq, p_q, p_k, p_vT,
                                                p_if, M_, NQKV, D_);
    }
    // 2) flash attention
    {
        dim3 grid(S_ / 128, H_, B_);
        attn_tf32<<<grid, 128, ATT_SMEM>>>(p_q, p_k, p_vT, p_o);
    }
    // 3) output projection + bias
    {
        dim3 grid(D_ / 128, M_ / 256);
        gemm_tf32<<<grid, 256, GEMM_SMEM>>>(p_o, p_wo, b_out, out,
                                            M_, D_, D_);
    }
}

// round 11
// speedup vs baseline: 2.0098x; 2.0098x over previous
#include <cuda_runtime.h>
#include <cuda_fp16.h>
#include <math.h>
#include <cstdint>

#define B_   2
#define S_   2048
#define D_   1024
#define H_   16
#define HD_  64
#define M_   (B_ * S_)      // 4096
#define NQKV (3 * D_)       // 3072

// ---------------- scratch (static device globals; no allocation) ----------
__device__ float  g_qkv[(size_t)M_ * NQKV];      // fp32 [B*S, 3D]
__device__ __half g_x16[(size_t)M_ * D_];
__device__ __half g_wq16[(size_t)NQKV * D_];
__device__ __half g_wo16[(size_t)D_ * D_];
__device__ __half g_q16[(size_t)M_ * D_];        // [B,H,S,64]
__device__ __half g_k16[(size_t)M_ * D_];        // [B,H,S,64]
__device__ __half g_v16[(size_t)M_ * D_];        // [B,H,S,64]
__device__ __half g_o16[(size_t)M_ * D_];        // [B*S, D]

// =====================  helpers  ===========================================
__device__ __forceinline__ uint32_t smem_u32(const void* p) {
    uint32_t a;
    asm("{ .reg .u64 t; cvta.to.shared.u64 t, %1; cvt.u32.u64 %0, t; }"
        : "=r"(a) : "l"(p));
    return a;
}
__device__ __forceinline__ void ldm_x4(uint32_t (&r)[4], uint32_t addr) {
    asm volatile("ldmatrix.sync.aligned.m8n8.x4.shared.b16 {%0,%1,%2,%3}, [%4];"
        : "=r"(r[0]), "=r"(r[1]), "=r"(r[2]), "=r"(r[3]) : "r"(addr));
}
__device__ __forceinline__ void ldm_x4_t(uint32_t (&r)[4], uint32_t addr) {
    asm volatile("ldmatrix.sync.aligned.m8n8.x4.trans.shared.b16 {%0,%1,%2,%3}, [%4];"
        : "=r"(r[0]), "=r"(r[1]), "=r"(r[2]), "=r"(r[3]) : "r"(addr));
}
__device__ __forceinline__ void mma_f16(float (&d)[4], const uint32_t (&a)[4],
                                        uint32_t b0, uint32_t b1) {
    asm volatile(
        "mma.sync.aligned.m16n8k16.row.col.f32.f16.f16.f32 "
        "{%0,%1,%2,%3}, {%4,%5,%6,%7}, {%8,%9}, {%0,%1,%2,%3};"
        : "+f"(d[0]), "+f"(d[1]), "+f"(d[2]), "+f"(d[3])
        : "r"(a[0]), "r"(a[1]), "r"(a[2]), "r"(a[3]), "r"(b0), "r"(b1));
}
__device__ __forceinline__ void cp16(uint32_t saddr, const void* gaddr) {
    asm volatile("cp.async.cg.shared.global [%0], [%1], 16;"
        :: "r"(saddr), "l"(gaddr));
}
#define CP_COMMIT() asm volatile("cp.async.commit_group;" ::: "memory")
#define CP_WAIT(n)  asm volatile("cp.async.wait_group %0;" :: "n"(n) : "memory")

__device__ __forceinline__ uint32_t pack_h2(float x0, float x1) {
    __half2 h = __floats2half2_rn(x0, x1);
    return *(uint32_t*)&h;
}

// ---------------------------------------------------------------------------
// cvt fp32 -> fp16 (rn), 8 elems/thread
// ---------------------------------------------------------------------------
__global__ void cvt_f16(const float* __restrict__ src, __half* __restrict__ dst,
                        int n8)
{
    int i = blockIdx.x * blockDim.x + threadIdx.x;
    if (i >= n8) return;
    float4 a = ((const float4*)src)[i * 2];
    float4 b = ((const float4*)src)[i * 2 + 1];
    uint4 o;
    o.x = pack_h2(a.x, a.y);
    o.y = pack_h2(a.z, a.w);
    o.z = pack_h2(b.x, b.y);
    o.w = pack_h2(b.z, b.w);
    ((uint4*)dst)[i] = o;
}

// ---------------------------------------------------------------------------
// GEMM (NT) fp16: C[m,n] = sum_k A[m,k]*B[n,k] (+bias), fp32 accum/out.
// CTA 256x128, 8 warps, warp tile 64x64. K-chunk 64 fp16 (128B rows),
// 3-stage cp.async, wait->sync->issue order.
// ---------------------------------------------------------------------------
#define G_BOFF 32768               // B tile offset (A = 256 rows x 128B)
#define G_STG  49152               // 48KB per stage
#define GEMM_SMEM (3 * G_STG)      // 147456

__global__ void __launch_bounds__(256, 1) gemm_f16(
    const __half* __restrict__ A, const __half* __restrict__ Bw,
    const float* __restrict__ bias, float* __restrict__ C,
    int M, int N, int K)
{
    extern __shared__ char sm[];
    const uint32_t sb = smem_u32(sm);
    const int tid  = threadIdx.x;
    const int lane = tid & 31;
    const int w    = tid >> 5;
    const int m0 = blockIdx.y * 256;
    const int n0 = blockIdx.x * 128;
    const int wm = (w & 3) * 64;
    const int wn = (w >> 2) * 64;

    float acc[4][8][4];
#pragma unroll
    for (int mi = 0; mi < 4; ++mi)
#pragma unroll
        for (int nj = 0; nj < 8; ++nj)
#pragma unroll
            for (int q = 0; q < 4; ++q) acc[mi][nj][q] = 0.f;

    const int nch = K >> 6;

    auto issue = [&](int kc, int stg) {
        uint32_t st = sb + stg * G_STG;
#pragma unroll
        for (int it = 0; it < 8; ++it) {          // A: 256 rows x 8 chunks
            int idx = tid + it * 256;
            int r = idx >> 3, c = idx & 7;
            uint32_t so = r * 128 + (((uint32_t)(c ^ (r & 7))) << 4);
            cp16(st + so, A + (size_t)(m0 + r) * K + kc * 64 + c * 8);
        }
#pragma unroll
        for (int it = 0; it < 4; ++it) {          // B: 128 rows x 8 chunks
            int idx = tid + it * 256;
            int r = idx >> 3, c = idx & 7;
            uint32_t so = r * 128 + (((uint32_t)(c ^ (r & 7))) << 4);
            cp16(st + G_BOFF + so, Bw + (size_t)(n0 + r) * K + kc * 64 + c * 8);
        }
        CP_COMMIT();
    };

    issue(0, 0);
    if (nch > 1) issue(1, 1);

    const int arow = (lane & 7) + ((lane >> 3) & 1) * 8;
    const int asel = lane >> 4;               // k8 selector for A
    const int brow = (lane & 7) + ((lane >> 4) & 1) * 8;
    const int bsel = (lane >> 3) & 1;         // k8 selector for B

    for (int kc = 0; kc < nch; ++kc) {
        if (kc + 1 < nch) { CP_WAIT(1); }
        else              { CP_WAIT(0); }
        __syncthreads();
        if (kc + 2 < nch) issue(kc + 2, (kc + 2) % 3);
        const uint32_t st = sb + (kc % 3) * G_STG;

#pragma unroll
        for (int ks = 0; ks < 4; ++ks) {
            // B frags: 4 x ldm_x4 -> 8 n8 frags
            uint32_t bf[8][2];
#pragma unroll
            for (int pi = 0; pi < 4; ++pi) {
                int r = wn + pi * 16 + brow;
                int gc = ks * 2 + bsel;
                uint32_t ad = st + G_BOFF + r * 128 +
                              (((uint32_t)(gc ^ (r & 7))) << 4);
                uint32_t tr[4];
                ldm_x4(tr, ad);
                bf[pi*2][0] = tr[0]; bf[pi*2][1] = tr[1];
                bf[pi*2+1][0] = tr[2]; bf[pi*2+1][1] = tr[3];
            }
#pragma unroll
            for (int mi = 0; mi < 4; ++mi) {
                int r = wm + mi * 16 + arow;
                int gc = ks * 2 + asel;
                uint32_t ad = st + r * 128 + (((uint32_t)(gc ^ (r & 7))) << 4);
                uint32_t af[4];
                ldm_x4(af, ad);
#pragma unroll
                for (int nj = 0; nj < 8; ++nj)
                    mma_f16(acc[mi][nj], af, bf[nj][0], bf[nj][1]);
            }
        }
    }

    const int g = lane >> 2;
    const int c0 = (lane & 3) * 2;
#pragma unroll
    for (int mi = 0; mi < 4; ++mi) {
#pragma unroll
        for (int nj = 0; nj < 8; ++nj) {
            int m = m0 + wm + mi * 16 + g;
            int n = n0 + wn + nj * 8 + c0;
            float b0 = bias ? bias[n] : 0.f;
            float b1 = bias ? bias[n + 1] : 0.f;
            float2 v0 = {acc[mi][nj][0] + b0, acc[mi][nj][1] + b1};
            float2 v1 = {acc[mi][nj][2] + b0, acc[mi][nj][3] + b1};
            *(float2*)(C + (size_t)m * N + n)       = v0;
            *(float2*)(C + (size_t)(m + 8) * N + n) = v1;
        }
    }
}

// ---------------------------------------------------------------------------
// RoPE: fp32 qkv -> fp16 q/k/v in [B,H,S,64]. Q pre-scaled by 1/sqrt(64).
// ---------------------------------------------------------------------------
__global__ void rope_f16(const float* __restrict__ qkv,
                         __half* __restrict__ q16, __half* __restrict__ k16,
                         __half* __restrict__ v16)
{
    int idx = blockIdx.x * blockDim.x + threadIdx.x;
    if (idx >= B_ * S_ * H_ * 32) return;
    int j = idx & 31;
    int h = (idx >> 5) & (H_ - 1);
    int s = (idx >> 9) & (S_ - 1);
    int b = idx >> 20;

    float tt  = (float)(2 * j) * (1.0f / (float)HD_);
    float inv = powf(10000.0f, -tt);
    float ang = (float)s * inv;
    float cs, sn;
    sincosf(ang, &sn, &cs);

    const float* row = qkv + ((size_t)(b * S_ + s)) * NQKV + h * HD_;
    float q1 = row[2 * j],          q2 = row[2 * j + 1];
    float k1 = row[D_ + 2 * j],     k2 = row[D_ + 2 * j + 1];
    float v1 = row[2 * D_ + 2 * j], v2 = row[2 * D_ + 2 * j + 1];

    size_t o = (((size_t)(b * H_ + h)) * S_ + s) * HD_;
    const float qs = 0.125f;
    q16[o + j]      = __float2half_rn((q1 * cs - q2 * sn) * qs);
    q16[o + 32 + j] = __float2half_rn((q1 * sn + q2 * cs) * qs);
    k16[o + j]      = __float2half_rn(k1 * cs - k2 * sn);
    k16[o + 32 + j] = __float2half_rn(k1 * sn + k2 * cs);
    __half2 vv = __floats2half2_rn(v1, v2);
    *(__half2*)(v16 + o + 2 * j) = vv;
}

// ---------------------------------------------------------------------------
// Flash attention fp16. 128 threads (4 warps), 32 q-rows/warp (q-tile 128),
// kv-tile 64, 3-stage cp.async, wait->sync->issue.
// stage = K (64r x 128B = 8KB) + V (64r x 128B = 8KB) = 16KB; Q staged in
// stage 0 before the pipeline starts.
// ---------------------------------------------------------------------------
#define A_VOFF 8192
#define A_STG  16384
#define ATT_SMEM (3 * A_STG)       // 49152

__global__ void __launch_bounds__(128, 2) attn_f16(
    const __half* __restrict__ q_, const __half* __restrict__ k_,
    const __half* __restrict__ v_, __half* __restrict__ o_)
{
    extern __shared__ char sm[];
    const uint32_t sb = smem_u32(sm);
    const int tid  = threadIdx.x;
    const int lane = tid & 31;
    const int w    = tid >> 5;
    const int g    = lane >> 2;
    const int t    = lane & 3;
    const int q0 = blockIdx.x * 128;
    const int h  = blockIdx.y;
    const int b  = blockIdx.z;
    const size_t bh = ((size_t)(b * H_ + h)) * S_;

    const int frow = (lane & 7) + ((lane >> 3) & 1) * 8;   // A/Q frag row
    const int fsel = lane >> 4;                            // A/Q k8 selector
    const int brow = (lane & 7) + ((lane >> 4) & 1) * 8;   // B/K frag row
    const int bsel = (lane >> 3) & 1;                      // B/K k8 selector
    const int vrow = (lane & 7) + ((lane >> 3) & 1) * 8;   // V frag row
    const int vsel = lane >> 4;                            // V col-chunk sel

    // --- stage Q (128 rows x 128B = 16KB) into stage 0, extract frags ---
#pragma unroll
    for (int it = 0; it < 8; ++it) {
        int idx = tid + it * 128;          // 1024: 128 rows x 8 chunks
        int r = idx >> 3, c = idx & 7;
        uint32_t so = r * 128 + (((uint32_t)(c ^ (r & 7))) << 4);
        cp16(sb + so, q_ + (bh + q0 + r) * HD_ + c * 8);
    }
    CP_COMMIT();
    CP_WAIT(0);
    __syncthreads();

    uint32_t qf[2][4][4];                  // [m16 half][k16 frag][regs]
#pragma unroll
    for (int rs = 0; rs < 2; ++rs) {
        int r = w * 32 + rs * 16 + frow;
#pragma unroll
        for (int ks = 0; ks < 4; ++ks) {
            int gc = ks * 2 + fsel;
            uint32_t ad = sb + r * 128 + (((uint32_t)(gc ^ (r & 7))) << 4);
            ldm_x4(qf[rs][ks], ad);
        }
    }
    __syncthreads();   // everyone done reading Q region

    auto issue_kv = [&](int n0k, int stg) {
        uint32_t st = sb + stg * A_STG;
#pragma unroll
        for (int it = 0; it < 4; ++it) {   // K: 64 rows x 8 chunks = 512
            int idx = tid + it * 128;
            int r = idx >> 3, c = idx & 7;
            uint32_t so = r * 128 + (((uint32_t)(c ^ (r & 7))) << 4);
            cp16(st + so, k_ + (bh + n0k + r) * HD_ + c * 8);
        }
#pragma unroll
        for (int it = 0; it < 4; ++it) {   // V: 64 rows x 8 chunks = 512
            int idx = tid + it * 128;
            int r = idx >> 3, c = idx & 7;
            uint32_t so = r * 128 + (((uint32_t)(c ^ (r & 7))) << 4);
            cp16(st + A_VOFF + so, v_ + (bh + n0k + r) * HD_ + c * 8);
        }
        CP_COMMIT();
    };

    issue_kv(0, 0);
    issue_kv(64, 1);

    float oacc[2][8][4];
    float mx[2][2] = {{-1e30f, -1e30f}, {-1e30f, -1e30f}};
    float li[2][2] = {{0.f, 0.f}, {0.f, 0.f}};
#pragma unroll
    for (int rs = 0; rs < 2; ++rs)
#pragma unroll
        for (int dj = 0; dj < 8; ++dj)
#pragma unroll
            for (int q = 0; q < 4; ++q) oacc[rs][dj][q] = 0.f;

    const int nkv = S_ / 64;
    for (int kc = 0; kc < nkv; ++kc) {
        if (kc + 1 < nkv) { CP_WAIT(1); }
        else              { CP_WAIT(0); }
        __syncthreads();
        if (kc + 2 < nkv) issue_kv((kc + 2) * 64, (kc + 2) % 3);
        const uint32_t st = sb + (kc % 3) * A_STG;

        // ---- S = Q K^T : per warp 32q x 64kv ----
        float s[2][8][4];
#pragma unroll
        for (int rs = 0; rs < 2; ++rs)
#pragma unroll
            for (int nj = 0; nj < 8; ++nj)
#pragma unroll
                for (int q = 0; q < 4; ++q) s[rs][nj][q] = 0.f;

#pragma unroll
        for (int ks = 0; ks < 4; ++ks) {
            uint32_t kf[8][2];
#pragma unroll
            for (int pi = 0; pi < 4; ++pi) {
                int r = pi * 16 + brow;
                int gc = ks * 2 + bsel;
                uint32_t ad = st + r * 128 + (((uint32_t)(gc ^ (r & 7))) << 4);
                uint32_t tr[4];
                ldm_x4(tr, ad);
                kf[pi*2][0] = tr[0]; kf[pi*2][1] = tr[1];
                kf[pi*2+1][0] = tr[2]; kf[pi*2+1][1] = tr[3];
            }
#pragma unroll
            for (int rs = 0; rs < 2; ++rs)
#pragma unroll
                for (int nj = 0; nj < 8; ++nj)
                    mma_f16(s[rs][nj], qf[rs][ks], kf[nj][0], kf[nj][1]);
        }

        // ---- online softmax ----
#pragma unroll
        for (int rs = 0; rs < 2; ++rs) {
#pragma unroll
            for (int ri = 0; ri < 2; ++ri) {
                float rm = -1e30f;
#pragma unroll
                for (int nj = 0; nj < 8; ++nj)
                    rm = fmaxf(rm, fmaxf(s[rs][nj][ri*2], s[rs][nj][ri*2+1]));
                rm = fmaxf(rm, __shfl_xor_sync(0xffffffffu, rm, 1));
                rm = fmaxf(rm, __shfl_xor_sync(0xffffffffu, rm, 2));
                float mn   = fmaxf(mx[rs][ri], rm);
                float corr = __expf(mx[rs][ri] - mn);
                mx[rs][ri] = mn;
                float rsum = 0.f;
#pragma unroll
                for (int nj = 0; nj < 8; ++nj) {
                    float p0 = __expf(s[rs][nj][ri*2]   - mn);
                    float p1 = __expf(s[rs][nj][ri*2+1] - mn);
                    s[rs][nj][ri*2] = p0; s[rs][nj][ri*2+1] = p1;
                    rsum += p0 + p1;
                }
                rsum += __shfl_xor_sync(0xffffffffu, rsum, 1);
                rsum += __shfl_xor_sync(0xffffffffu, rsum, 2);
                li[rs][ri] = li[rs][ri] * corr + rsum;
#pragma unroll
                for (int dj = 0; dj < 8; ++dj) {
                    oacc[rs][dj][ri*2]   *= corr;
                    oacc[rs][dj][ri*2+1] *= corr;
                }
            }
        }

        // ---- O += P V : P packed to fp16 A-frags; V via ldmatrix.trans ----
#pragma unroll
        for (int kk = 0; kk < 4; ++kk) {   // k16 tiles over kv 64
            uint32_t pa[2][4];
#pragma unroll
            for (int rs = 0; rs < 2; ++rs) {
                pa[rs][0] = pack_h2(s[rs][kk*2][0],   s[rs][kk*2][1]);
                pa[rs][1] = pack_h2(s[rs][kk*2][2],   s[rs][kk*2][3]);
                pa[rs][2] = pack_h2(s[rs][kk*2+1][0], s[rs][kk*2+1][1]);
                pa[rs][3] = pack_h2(s[rs][kk*2+1][2], s[rs][kk*2+1][3]);
            }
#pragma unroll
            for (int pj = 0; pj < 4; ++pj) {   // d-chunks: 2 dj per ldm
                int r = kk * 16 + vrow;
                int gc = pj * 2 + vsel;
                uint32_t ad = st + A_VOFF + r * 128 +
                              (((uint32_t)(gc ^ (r & 7))) << 4);
                uint32_t tv[4];
                ldm_x4_t(tv, ad);
#pragma unroll
                for (int rs = 0; rs < 2; ++rs) {
                    mma_f16(oacc[rs][pj*2],   pa[rs], tv[0], tv[1]);
                    mma_f16(oacc[rs][pj*2+1], pa[rs], tv[2], tv[3]);
                }
            }
        }
    }

    // ---- epilogue: normalize, fp16 store [B*S, D] ----
#pragma unroll
    for (int rs = 0; rs < 2; ++rs) {
#pragma unroll
        for (int ri = 0; ri < 2; ++ri) {
            float inv = 1.0f / li[rs][ri];
            int srow = q0 + w * 32 + rs * 16 + g + ri * 8;
            size_t rowo = ((size_t)(b * S_) + srow) * D_ + h * HD_;
#pragma unroll
            for (int dj = 0; dj < 8; ++dj) {
                int c = dj * 8 + 2 * t;
                uint32_t hp = pack_h2(oacc[rs][dj][ri*2] * inv,
                                      oacc[rs][dj][ri*2+1] * inv);
                *(uint32_t*)(o_ + rowo + c) = hp;
            }
        }
    }
}

// ---------------------------------------------------------------------------
extern "C" void kernel_launch(void* const* d_in, const int* in_sizes, int n_in,
                              void* d_out, int out_size)
{
    (void)in_sizes; (void)n_in; (void)out_size;
    const float* x     = (const float*)d_in[0];
    const float* w_qkv = (const float*)d_in[1];
    const float* w_out = (const float*)d_in[2];
    const float* b_out = (const float*)d_in[3];
    float* out = (float*)d_out;

    float* p_qkv;
    __half *p_x, *p_wq, *p_wo, *p_q, *p_k, *p_v, *p_o;
    cudaGetSymbolAddress((void**)&p_qkv, g_qkv);
    cudaGetSymbolAddress((void**)&p_x,   g_x16);
    cudaGetSymbolAddress((void**)&p_wq,  g_wq16);
    cudaGetSymbolAddress((void**)&p_wo,  g_wo16);
    cudaGetSymbolAddress((void**)&p_q,   g_q16);
    cudaGetSymbolAddress((void**)&p_k,   g_k16);
    cudaGetSymbolAddress((void**)&p_v,   g_v16);
    cudaGetSymbolAddress((void**)&p_o,   g_o16);

    cudaFuncSetAttribute(gemm_f16,
        cudaFuncAttributeMaxDynamicSharedMemorySize, GEMM_SMEM);
    cudaFuncSetAttribute(attn_f16,
        cudaFuncAttributeMaxDynamicSharedMemorySize, ATT_SMEM);

    // 0) convert inputs / weights to fp16
    {
        int n8;
        n8 = (M_ * D_) / 8;
        cvt_f16<<<(n8 + 255) / 256, 256>>>(x, p_x, n8);
        n8 = (NQKV * D_) / 8;
        cvt_f16<<<(n8 + 255) / 256, 256>>>(w_qkv, p_wq, n8);
        n8 = (D_ * D_) / 8;
        cvt_f16<<<(n8 + 255) / 256, 256>>>(w_out, p_wo, n8);
    }
    // 1) QKV projection (fp16 in, fp32 out)
    {
        dim3 grid(NQKV / 128, M_ / 256);
        gemm_f16<<<grid, 256, GEMM_SMEM>>>(p_x, p_wq, nullptr, p_qkv,
                                           M_, NQKV, D_);
    }
    // 2) RoPE -> fp16 q/k/v [B,H,S,64]
    {
        int total = B_ * S_ * H_ * 32;
        rope_f16<<<(total + 255) / 256, 256>>>(p_qkv, p_q, p_k, p_v);
    }
    // 3) flash attention (fp16 tensor cores)
    {
        dim3 grid(S_ / 128, H_, B_);
        attn_f16<<<grid, 128, ATT_SMEM>>>(p_q, p_k, p_v, p_o);
    }
    // 4) output projection + bias
    {
        dim3 grid(D_ / 128, M_ / 256);
        gemm_f16<<<grid, 256, GEMM_SMEM>>>(p_o, p_wo, b_out, out,
                                           M_, D_, D_);
    }
}

// round 12
// speedup vs baseline: 2.0884x; 1.0391x over previous
#include <cuda_runtime.h>
#include <cuda_fp16.h>
#include <math.h>
#include <cstdint>

#define B_   2
#define S_   2048
#define D_   1024
#define H_   16
#define HD_  64
#define M_   (B_ * S_)      // 4096
#define NQKV (3 * D_)       // 3072

// ---------------- scratch (static device globals; no allocation) ----------
__device__ float  g_qkv[(size_t)M_ * NQKV];      // fp32 [B*S, 3D]
__device__ __half g_x16[(size_t)M_ * D_];
__device__ __half g_wq16[(size_t)NQKV * D_];
__device__ __half g_wo16[(size_t)D_ * D_];
__device__ __half g_q16[(size_t)M_ * D_];        // [B,H,S,64]
__device__ __half g_k16[(size_t)M_ * D_];        // [B,H,S,64]
__device__ __half g_v16[(size_t)M_ * D_];        // [B,H,S,64]
__device__ __half g_o16[(size_t)M_ * D_];        // [B*S, D]
__device__ float  g_invfreq[32];

// =====================  helpers  ===========================================
__device__ __forceinline__ uint32_t smem_u32(const void* p) {
    uint32_t a;
    asm("{ .reg .u64 t; cvta.to.shared.u64 t, %1; cvt.u32.u64 %0, t; }"
        : "=r"(a) : "l"(p));
    return a;
}
__device__ __forceinline__ void ldm_x4(uint32_t (&r)[4], uint32_t addr) {
    asm volatile("ldmatrix.sync.aligned.m8n8.x4.shared.b16 {%0,%1,%2,%3}, [%4];"
        : "=r"(r[0]), "=r"(r[1]), "=r"(r[2]), "=r"(r[3]) : "r"(addr));
}
__device__ __forceinline__ void ldm_x4_t(uint32_t (&r)[4], uint32_t addr) {
    asm volatile("ldmatrix.sync.aligned.m8n8.x4.trans.shared.b16 {%0,%1,%2,%3}, [%4];"
        : "=r"(r[0]), "=r"(r[1]), "=r"(r[2]), "=r"(r[3]) : "r"(addr));
}
__device__ __forceinline__ void mma_f16(float (&d)[4], const uint32_t (&a)[4],
                                        uint32_t b0, uint32_t b1) {
    asm volatile(
        "mma.sync.aligned.m16n8k16.row.col.f32.f16.f16.f32 "
        "{%0,%1,%2,%3}, {%4,%5,%6,%7}, {%8,%9}, {%0,%1,%2,%3};"
        : "+f"(d[0]), "+f"(d[1]), "+f"(d[2]), "+f"(d[3])
        : "r"(a[0]), "r"(a[1]), "r"(a[2]), "r"(a[3]), "r"(b0), "r"(b1));
}
__device__ __forceinline__ void cp16(uint32_t saddr, const void* gaddr) {
    asm volatile("cp.async.cg.shared.global [%0], [%1], 16;"
        :: "r"(saddr), "l"(gaddr));
}
#define CP_COMMIT() asm volatile("cp.async.commit_group;" ::: "memory")
#define CP_WAIT(n)  asm volatile("cp.async.wait_group %0;" :: "n"(n) : "memory")

__device__ __forceinline__ uint32_t pack_h2(float x0, float x1) {
    __half2 h = __floats2half2_rn(x0, x1);
    return *(uint32_t*)&h;
}

// ---------------------------------------------------------------------------
__global__ void init_invfreq(float* invf) {
    int j = threadIdx.x;                    // 0..31
    float tt = (float)(2 * j) * (1.0f / (float)HD_);
    invf[j] = powf(10000.0f, -tt);
}

// ---------------------------------------------------------------------------
// cvt fp32 -> fp16 (rn), 8 elems/thread
// ---------------------------------------------------------------------------
__global__ void cvt_f16(const float* __restrict__ src, __half* __restrict__ dst,
                        int n8)
{
    int i = blockIdx.x * blockDim.x + threadIdx.x;
    if (i >= n8) return;
    float4 a = ((const float4*)src)[i * 2];
    float4 b = ((const float4*)src)[i * 2 + 1];
    uint4 o;
    o.x = pack_h2(a.x, a.y);
    o.y = pack_h2(a.z, a.w);
    o.z = pack_h2(b.x, b.y);
    o.w = pack_h2(b.z, b.w);
    ((uint4*)dst)[i] = o;
}

// ---------------------------------------------------------------------------
// GEMM (NT) fp16: C[m,n] = sum_k A[m,k]*B[n,k] (+bias), fp32 accum/out.
// CTA 128x128, 8 warps, warp tile 64x32. K-chunk 64 fp16 (128B rows),
// 3-stage cp.async (32KB/stage), 2 CTAs/SM, wait->sync->issue order.
// ---------------------------------------------------------------------------
#define G_BOFF 16384               // B tile offset (A = 128 rows x 128B)
#define G_STG  32768               // 32KB per stage
#define GEMM_SMEM (3 * G_STG)      // 98304

__global__ void __launch_bounds__(256, 2) gemm_f16(
    const __half* __restrict__ A, const __half* __restrict__ Bw,
    const float* __restrict__ bias, float* __restrict__ C,
    int M, int N, int K)
{
    extern __shared__ char sm[];
    const uint32_t sb = smem_u32(sm);
    const int tid  = threadIdx.x;
    const int lane = tid & 31;
    const int w    = tid >> 5;
    const int m0 = blockIdx.y * 128;
    const int n0 = blockIdx.x * 128;
    const int wm = (w & 1) * 64;
    const int wn = (w >> 1) * 32;

    float acc[4][4][4];
#pragma unroll
    for (int mi = 0; mi < 4; ++mi)
#pragma unroll
        for (int nj = 0; nj < 4; ++nj)
#pragma unroll
            for (int q = 0; q < 4; ++q) acc[mi][nj][q] = 0.f;

    const int nch = K >> 6;

    auto issue = [&](int kc, int stg) {
        uint32_t st = sb + stg * G_STG;
#pragma unroll
        for (int it = 0; it < 4; ++it) {          // A: 128 rows x 8 chunks
            int idx = tid + it * 256;
            int r = idx >> 3, c = idx & 7;
            uint32_t so = r * 128 + (((uint32_t)(c ^ (r & 7))) << 4);
            cp16(st + so, A + (size_t)(m0 + r) * K + kc * 64 + c * 8);
        }
#pragma unroll
        for (int it = 0; it < 4; ++it) {          // B: 128 rows x 8 chunks
            int idx = tid + it * 256;
            int r = idx >> 3, c = idx & 7;
            uint32_t so = r * 128 + (((uint32_t)(c ^ (r & 7))) << 4);
            cp16(st + G_BOFF + so, Bw + (size_t)(n0 + r) * K + kc * 64 + c * 8);
        }
        CP_COMMIT();
    };

    issue(0, 0);
    if (nch > 1) issue(1, 1);

    const int arow = (lane & 7) + ((lane >> 3) & 1) * 8;
    const int asel = lane >> 4;               // k8 selector for A
    const int brow = (lane & 7) + ((lane >> 4) & 1) * 8;
    const int bsel = (lane >> 3) & 1;         // k8 selector for B

    for (int kc = 0; kc < nch; ++kc) {
        if (kc + 1 < nch) { CP_WAIT(1); }
        else              { CP_WAIT(0); }
        __syncthreads();
        if (kc + 2 < nch) issue(kc + 2, (kc + 2) % 3);
        const uint32_t st = sb + (kc % 3) * G_STG;

#pragma unroll
        for (int ks = 0; ks < 4; ++ks) {
            // B frags: 2 x ldm_x4 -> 4 n8 frags
            uint32_t bf[4][2];
#pragma unroll
            for (int pi = 0; pi < 2; ++pi) {
                int r = wn + pi * 16 + brow;
                int gc = ks * 2 + bsel;
                uint32_t ad = st + G_BOFF + r * 128 +
                              (((uint32_t)(gc ^ (r & 7))) << 4);
                uint32_t tr[4];
                ldm_x4(tr, ad);
                bf[pi*2][0] = tr[0]; bf[pi*2][1] = tr[1];
                bf[pi*2+1][0] = tr[2]; bf[pi*2+1][1] = tr[3];
            }
#pragma unroll
            for (int mi = 0; mi < 4; ++mi) {
                int r = wm + mi * 16 + arow;
                int gc = ks * 2 + asel;
                uint32_t ad = st + r * 128 + (((uint32_t)(gc ^ (r & 7))) << 4);
                uint32_t af[4];
                ldm_x4(af, ad);
#pragma unroll
                for (int nj = 0; nj < 4; ++nj)
                    mma_f16(acc[mi][nj], af, bf[nj][0], bf[nj][1]);
            }
        }
    }

    const int g = lane >> 2;
    const int c0 = (lane & 3) * 2;
#pragma unroll
    for (int mi = 0; mi < 4; ++mi) {
#pragma unroll
        for (int nj = 0; nj < 4; ++nj) {
            int m = m0 + wm + mi * 16 + g;
            int n = n0 + wn + nj * 8 + c0;
            float b0 = bias ? bias[n] : 0.f;
            float b1 = bias ? bias[n + 1] : 0.f;
            float2 v0 = {acc[mi][nj][0] + b0, acc[mi][nj][1] + b1};
            float2 v1 = {acc[mi][nj][2] + b0, acc[mi][nj][3] + b1};
            *(float2*)(C + (size_t)m * N + n)       = v0;
            *(float2*)(C + (size_t)(m + 8) * N + n) = v1;
        }
    }
}

// ---------------------------------------------------------------------------
// RoPE: fp32 qkv -> fp16 q/k/v in [B,H,S,64]. Q pre-scaled by 1/sqrt(64).
// invfreq from table (bit-identical to inline powf).
// ---------------------------------------------------------------------------
__global__ void rope_f16(const float* __restrict__ qkv,
                         const float* __restrict__ invfreq,
                         __half* __restrict__ q16, __half* __restrict__ k16,
                         __half* __restrict__ v16)
{
    int idx = blockIdx.x * blockDim.x + threadIdx.x;
    if (idx >= B_ * S_ * H_ * 32) return;
    int j = idx & 31;
    int h = (idx >> 5) & (H_ - 1);
    int s = (idx >> 9) & (S_ - 1);
    int b = idx >> 20;

    float ang = (float)s * invfreq[j];
    float cs, sn;
    sincosf(ang, &sn, &cs);

    const float* row = qkv + ((size_t)(b * S_ + s)) * NQKV + h * HD_;
    float q1 = row[2 * j],          q2 = row[2 * j + 1];
    float k1 = row[D_ + 2 * j],     k2 = row[D_ + 2 * j + 1];
    float v1 = row[2 * D_ + 2 * j], v2 = row[2 * D_ + 2 * j + 1];

    size_t o = (((size_t)(b * H_ + h)) * S_ + s) * HD_;
    const float qs = 0.125f;
    q16[o + j]      = __float2half_rn((q1 * cs - q2 * sn) * qs);
    q16[o + 32 + j] = __float2half_rn((q1 * sn + q2 * cs) * qs);
    k16[o + j]      = __float2half_rn(k1 * cs - k2 * sn);
    k16[o + 32 + j] = __float2half_rn(k1 * sn + k2 * cs);
    __half2 vv = __floats2half2_rn(v1, v2);
    *(__half2*)(v16 + o + 2 * j) = vv;
}

// ---------------------------------------------------------------------------
// Flash attention fp16. 128 threads (4 warps), 32 q-rows/warp (q-tile 128),
// kv-tile 64, 3-stage cp.async, wait->sync->issue. (unchanged from round 11)
// ---------------------------------------------------------------------------
#define A_VOFF 8192
#define A_STG  16384
#define ATT_SMEM (3 * A_STG)       // 49152

__global__ void __launch_bounds__(128, 2) attn_f16(
    const __half* __restrict__ q_, const __half* __restrict__ k_,
    const __half* __restrict__ v_, __half* __restrict__ o_)
{
    extern __shared__ char sm[];
    const uint32_t sb = smem_u32(sm);
    const int tid  = threadIdx.x;
    const int lane = tid & 31;
    const int w    = tid >> 5;
    const int g    = lane >> 2;
    const int t    = lane & 3;
    const int q0 = blockIdx.x * 128;
    const int h  = blockIdx.y;
    const int b  = blockIdx.z;
    const size_t bh = ((size_t)(b * H_ + h)) * S_;

    const int frow = (lane & 7) + ((lane >> 3) & 1) * 8;
    const int fsel = lane >> 4;
    const int brow = (lane & 7) + ((lane >> 4) & 1) * 8;
    const int bsel = (lane >> 3) & 1;
    const int vrow = (lane & 7) + ((lane >> 3) & 1) * 8;
    const int vsel = lane >> 4;

#pragma unroll
    for (int it = 0; it < 8; ++it) {
        int idx = tid + it * 128;
        int r = idx >> 3, c = idx & 7;
        uint32_t so = r * 128 + (((uint32_t)(c ^ (r & 7))) << 4);
        cp16(sb + so, q_ + (bh + q0 + r) * HD_ + c * 8);
    }
    CP_COMMIT();
    CP_WAIT(0);
    __syncthreads();

    uint32_t qf[2][4][4];
#pragma unroll
    for (int rs = 0; rs < 2; ++rs) {
        int r = w * 32 + rs * 16 + frow;
#pragma unroll
        for (int ks = 0; ks < 4; ++ks) {
            int gc = ks * 2 + fsel;
            uint32_t ad = sb + r * 128 + (((uint32_t)(gc ^ (r & 7))) << 4);
            ldm_x4(qf[rs][ks], ad);
        }
    }
    __syncthreads();

    auto issue_kv = [&](int n0k, int stg) {
        uint32_t st = sb + stg * A_STG;
#pragma unroll
        for (int it = 0; it < 4; ++it) {
            int idx = tid + it * 128;
            int r = idx >> 3, c = idx & 7;
            uint32_t so = r * 128 + (((uint32_t)(c ^ (r & 7))) << 4);
            cp16(st + so, k_ + (bh + n0k + r) * HD_ + c * 8);
        }
#pragma unroll
        for (int it = 0; it < 4; ++it) {
            int idx = tid + it * 128;
            int r = idx >> 3, c = idx & 7;
            uint32_t so = r * 128 + (((uint32_t)(c ^ (r & 7))) << 4);
            cp16(st + A_VOFF + so, v_ + (bh + n0k + r) * HD_ + c * 8);
        }
        CP_COMMIT();
    };

    issue_kv(0, 0);
    issue_kv(64, 1);

    float oacc[2][8][4];
    float mx[2][2] = {{-1e30f, -1e30f}, {-1e30f, -1e30f}};
    float li[2][2] = {{0.f, 0.f}, {0.f, 0.f}};
#pragma unroll
    for (int rs = 0; rs < 2; ++rs)
#pragma unroll
        for (int dj = 0; dj < 8; ++dj)
#pragma unroll
            for (int q = 0; q < 4; ++q) oacc[rs][dj][q] = 0.f;

    const int nkv = S_ / 64;
    for (int kc = 0; kc < nkv; ++kc) {
        if (kc + 1 < nkv) { CP_WAIT(1); }
        else              { CP_WAIT(0); }
        __syncthreads();
        if (kc + 2 < nkv) issue_kv((kc + 2) * 64, (kc + 2) % 3);
        const uint32_t st = sb + (kc % 3) * A_STG;

        float s[2][8][4];
#pragma unroll
        for (int rs = 0; rs < 2; ++rs)
#pragma unroll
            for (int nj = 0; nj < 8; ++nj)
#pragma unroll
                for (int q = 0; q < 4; ++q) s[rs][nj][q] = 0.f;

#pragma unroll
        for (int ks = 0; ks < 4; ++ks) {
            uint32_t kf[8][2];
#pragma unroll
            for (int pi = 0; pi < 4; ++pi) {
                int r = pi * 16 + brow;
                int gc = ks * 2 + bsel;
                uint32_t ad = st + r * 128 + (((uint32_t)(gc ^ (r & 7))) << 4);
                uint32_t tr[4];
                ldm_x4(tr, ad);
                kf[pi*2][0] = tr[0]; kf[pi*2][1] = tr[1];
                kf[pi*2+1][0] = tr[2]; kf[pi*2+1][1] = tr[3];
            }
#pragma unroll
            for (int rs = 0; rs < 2; ++rs)
#pragma unroll
                for (int nj = 0; nj < 8; ++nj)
                    mma_f16(s[rs][nj], qf[rs][ks], kf[nj][0], kf[nj][1]);
        }

#pragma unroll
        for (int rs = 0; rs < 2; ++rs) {
#pragma unroll
            for (int ri = 0; ri < 2; ++ri) {
                float rm = -1e30f;
#pragma unroll
                for (int nj = 0; nj < 8; ++nj)
                    rm = fmaxf(rm, fmaxf(s[rs][nj][ri*2], s[rs][nj][ri*2+1]));
                rm = fmaxf(rm, __shfl_xor_sync(0xffffffffu, rm, 1));
                rm = fmaxf(rm, __shfl_xor_sync(0xffffffffu, rm, 2));
                float mn   = fmaxf(mx[rs][ri], rm);
                float corr = __expf(mx[rs][ri] - mn);
                mx[rs][ri] = mn;
                float rsum = 0.f;
#pragma unroll
                for (int nj = 0; nj < 8; ++nj) {
                    float p0 = __expf(s[rs][nj][ri*2]   - mn);
                    float p1 = __expf(s[rs][nj][ri*2+1] - mn);
                    s[rs][nj][ri*2] = p0; s[rs][nj][ri*2+1] = p1;
                    rsum += p0 + p1;
                }
                rsum += __shfl_xor_sync(0xffffffffu, rsum, 1);
                rsum += __shfl_xor_sync(0xffffffffu, rsum, 2);
                li[rs][ri] = li[rs][ri] * corr + rsum;
#pragma unroll
                for (int dj = 0; dj < 8; ++dj) {
                    oacc[rs][dj][ri*2]   *= corr;
                    oacc[rs][dj][ri*2+1] *= corr;
                }
            }
        }

#pragma unroll
        for (int kk = 0; kk < 4; ++kk) {
            uint32_t pa[2][4];
#pragma unroll
            for (int rs = 0; rs < 2; ++rs) {
                pa[rs][0] = pack_h2(s[rs][kk*2][0],   s[rs][kk*2][1]);
                pa[rs][1] = pack_h2(s[rs][kk*2][2],   s[rs][kk*2][3]);
                pa[rs][2] = pack_h2(s[rs][kk*2+1][0], s[rs][kk*2+1][1]);
                pa[rs][3] = pack_h2(s[rs][kk*2+1][2], s[rs][kk*2+1][3]);
            }
#pragma unroll
            for (int pj = 0; pj < 4; ++pj) {
                int r = kk * 16 + vrow;
                int gc = pj * 2 + vsel;
                uint32_t ad = st + A_VOFF + r * 128 +
                              (((uint32_t)(gc ^ (r & 7))) << 4);
                uint32_t tv[4];
                ldm_x4_t(tv, ad);
#pragma unroll
                for (int rs = 0; rs < 2; ++rs) {
                    mma_f16(oacc[rs][pj*2],   pa[rs], tv[0], tv[1]);
                    mma_f16(oacc[rs][pj*2+1], pa[rs], tv[2], tv[3]);
                }
            }
        }
    }

#pragma unroll
    for (int rs = 0; rs < 2; ++rs) {
#pragma unroll
        for (int ri = 0; ri < 2; ++ri) {
            float inv = 1.0f / li[rs][ri];
            int srow = q0 + w * 32 + rs * 16 + g + ri * 8;
            size_t rowo = ((size_t)(b * S_) + srow) * D_ + h * HD_;
#pragma unroll
            for (int dj = 0; dj < 8; ++dj) {
                int c = dj * 8 + 2 * t;
                uint32_t hp = pack_h2(oacc[rs][dj][ri*2] * inv,
                                      oacc[rs][dj][ri*2+1] * inv);
                *(uint32_t*)(o_ + rowo + c) = hp;
            }
        }
    }
}

// ---------------------------------------------------------------------------
extern "C" void kernel_launch(void* const* d_in, const int* in_sizes, int n_in,
                              void* d_out, int out_size)
{
    (void)in_sizes; (void)n_in; (void)out_size;
    const float* x     = (const float*)d_in[0];
    const float* w_qkv = (const float*)d_in[1];
    const float* w_out = (const float*)d_in[2];
    const float* b_out = (const float*)d_in[3];
    float* out = (float*)d_out;

    float *p_qkv, *p_if;
    __half *p_x, *p_wq, *p_wo, *p_q, *p_k, *p_v, *p_o;
    cudaGetSymbolAddress((void**)&p_qkv, g_qkv);
    cudaGetSymbolAddress((void**)&p_if,  g_invfreq);
    cudaGetSymbolAddress((void**)&p_x,   g_x16);
    cudaGetSymbolAddress((void**)&p_wq,  g_wq16);
    cudaGetSymbolAddress((void**)&p_wo,  g_wo16);
    cudaGetSymbolAddress((void**)&p_q,   g_q16);
    cudaGetSymbolAddress((void**)&p_k,   g_k16);
    cudaGetSymbolAddress((void**)&p_v,   g_v16);
    cudaGetSymbolAddress((void**)&p_o,   g_o16);

    cudaFuncSetAttribute(gemm_f16,
        cudaFuncAttributeMaxDynamicSharedMemorySize, GEMM_SMEM);
    cudaFuncSetAttribute(attn_f16,
        cudaFuncAttributeMaxDynamicSharedMemorySize, ATT_SMEM);

    // 0) rope table + convert inputs / weights to fp16
    init_invfreq<<<1, 32>>>(p_if);
    {
        int n8;
        n8 = (M_ * D_) / 8;
        cvt_f16<<<(n8 + 255) / 256, 256>>>(x, p_x, n8);
        n8 = (NQKV * D_) / 8;
        cvt_f16<<<(n8 + 255) / 256, 256>>>(w_qkv, p_wq, n8);
        n8 = (D_ * D_) / 8;
        cvt_f16<<<(n8 + 255) / 256, 256>>>(w_out, p_wo, n8);
    }
    // 1) QKV projection (fp16 in, fp32 out)
    {
        dim3 grid(NQKV / 128, M_ / 128);
        gemm_f16<<<grid, 256, GEMM_SMEM>>>(p_x, p_wq, nullptr, p_qkv,
                                           M_, NQKV, D_);
    }
    // 2) RoPE -> fp16 q/k/v [B,H,S,64]
    {
        int total = B_ * S_ * H_ * 32;
        rope_f16<<<(total + 255) / 256, 256>>>(p_qkv, p_if, p_q, p_k, p_v);
    }
    // 3) flash attention (fp16 tensor cores)
    {
        dim3 grid(S_ / 128, H_, B_);
        attn_f16<<<grid, 128, ATT_SMEM>>>(p_q, p_k, p_v, p_o);
    }
    // 4) output projection + bias
    {
        dim3 grid(D_ / 128, M_ / 128);
        gemm_f16<<<grid, 256, GEMM_SMEM>>>(p_o, p_wo, b_out, out,
                                           M_, D_, D_);
    }
}